// round 1
// baseline (speedup 1.0000x reference)
#include <cuda_runtime.h>
#include <cstdint>

// ---------------- problem constants (guarded at runtime) ----------------
#define MAX_NODES 100000
#define DIM_D 256
#define DIM_O 128

// ---------------- scratch (device globals; no runtime alloc) ------------
__device__ __align__(16) float g_agg[(size_t)MAX_NODES * DIM_D];   // 102.4 MB
__device__ __align__(16) float g_h[(size_t)MAX_NODES * DIM_O];     // 51.2 MB

// ---------------- zero agg ----------------------------------------------
__global__ void zero_kernel(float4* __restrict__ p, int n4) {
    int i = blockIdx.x * blockDim.x + threadIdx.x;
    if (i < n4) p[i] = make_float4(0.f, 0.f, 0.f, 0.f);
}

// ---------------- scatter: agg[dst] += x[src] * w ------------------------
// 64 lanes per edge, float4 per lane (64*16B = 1024B = one 256-float row).
__global__ void scatter_kernel(const float4* __restrict__ x4,
                               const int* __restrict__ mei, int E_msg,
                               const int* __restrict__ tei,
                               const float* __restrict__ tw, int E_tgt,
                               float4* __restrict__ agg4) {
    int t = blockIdx.x * blockDim.x + threadIdx.x;
    int g = t >> 6;          // edge id
    int lane = t & 63;       // float4 slot within the 256-float row
    int E = E_msg + E_tgt;
    if (g >= E) return;

    int src, dst; float w;
    if (g < E_msg) {
        src = __ldg(&mei[g]);
        dst = __ldg(&mei[E_msg + g]);
        w = 1.0f;
    } else {
        int j = g - E_msg;
        // target edges are FLIPPED: src = tei[1][j], dst = tei[0][j]
        src = __ldg(&tei[E_tgt + j]);
        dst = __ldg(&tei[j]);
        w = __ldg(&tw[j]);
    }

    float4 v = __ldg(&x4[(long)src * 64 + lane]);
    float4 r;
    r.x = v.x * w; r.y = v.y * w; r.z = v.z * w; r.w = v.w * w;

    float* p = (float*)&agg4[(long)dst * 64 + lane];
    asm volatile("red.global.add.v4.f32 [%0], {%1,%2,%3,%4};"
                 :: "l"(p), "f"(r.x), "f"(r.y), "f"(r.z), "f"(r.w)
                 : "memory");
}

// ---------------- fused GEMM: C = relu(A0@W0 [+ A1@W1] + bias) -----------
// A: [M,K] row-major.  W: [K,128] row-major.  C: [M,128].
// Block tile 128x128, BK=16, 256 threads, 8x8 microtile per thread.
#define BM 128
#define BN 128
#define BK 16

__global__ __launch_bounds__(256, 1)
void gemm_bias_relu(const float* __restrict__ A0, const float* __restrict__ W0,
                    const float* __restrict__ A1, const float* __restrict__ W1,
                    const float* __restrict__ bias, float* __restrict__ C,
                    int M, int K) {
    __shared__ float As[BK][BM];
    __shared__ float Bs[BK][BN];

    int tid = threadIdx.x;
    int m0 = blockIdx.x * BM;
    int ty = tid >> 4;   // 0..15 -> rows ty*8..ty*8+7
    int tx = tid & 15;   // 0..15 -> cols tx*8..tx*8+7

    float acc[8][8];
    #pragma unroll
    for (int i = 0; i < 8; i++)
        #pragma unroll
        for (int j = 0; j < 8; j++) acc[i][j] = 0.f;

    #pragma unroll 1
    for (int pass = 0; pass < 2; ++pass) {
        const float* A = pass ? A1 : A0;
        const float* W = pass ? W1 : W0;
        if (A == nullptr) break;

        #pragma unroll 1
        for (int kk = 0; kk < K; kk += BK) {
            // ---- load A tile (128 rows x 16 cols), transposed into As[k][row]
            #pragma unroll
            for (int i = 0; i < 2; ++i) {
                int idx = tid + i * 256;   // float4 index, 0..511
                int r = idx >> 2;          // row 0..127
                int c4 = idx & 3;          // which float4 within the 16 cols
                float4 v = make_float4(0.f, 0.f, 0.f, 0.f);
                int gr = m0 + r;
                if (gr < M)
                    v = *(const float4*)&A[(long)gr * K + kk + c4 * 4];
                As[c4 * 4 + 0][r] = v.x;
                As[c4 * 4 + 1][r] = v.y;
                As[c4 * 4 + 2][r] = v.z;
                As[c4 * 4 + 3][r] = v.w;
            }
            // ---- load W tile (16 rows x 128 cols)
            #pragma unroll
            for (int i = 0; i < 2; ++i) {
                int idx = tid + i * 256;   // float4 index, 0..511
                int r = idx >> 5;          // row 0..15
                int c4 = idx & 31;         // float4 within 128 cols
                *(float4*)&Bs[r][c4 * 4] =
                    *(const float4*)&W[(long)(kk + r) * 128 + c4 * 4];
            }
            __syncthreads();

            #pragma unroll
            for (int k = 0; k < BK; ++k) {
                float ra[8], rb[8];
                *(float4*)&ra[0] = *(const float4*)&As[k][ty * 8];
                *(float4*)&ra[4] = *(const float4*)&As[k][ty * 8 + 4];
                *(float4*)&rb[0] = *(const float4*)&Bs[k][tx * 8];
                *(float4*)&rb[4] = *(const float4*)&Bs[k][tx * 8 + 4];
                #pragma unroll
                for (int i = 0; i < 8; i++)
                    #pragma unroll
                    for (int j = 0; j < 8; j++)
                        acc[i][j] += ra[i] * rb[j];
            }
            __syncthreads();
        }
    }

    // ---- epilogue: bias + relu, vectorized stores
    float bvals[8];
    #pragma unroll
    for (int j = 0; j < 8; j++) bvals[j] = bias[tx * 8 + j];

    #pragma unroll
    for (int i = 0; i < 8; i++) {
        int gr = m0 + ty * 8 + i;
        if (gr >= M) continue;
        float4 v0, v1;
        v0.x = fmaxf(acc[i][0] + bvals[0], 0.f);
        v0.y = fmaxf(acc[i][1] + bvals[1], 0.f);
        v0.z = fmaxf(acc[i][2] + bvals[2], 0.f);
        v0.w = fmaxf(acc[i][3] + bvals[3], 0.f);
        v1.x = fmaxf(acc[i][4] + bvals[4], 0.f);
        v1.y = fmaxf(acc[i][5] + bvals[5], 0.f);
        v1.z = fmaxf(acc[i][6] + bvals[6], 0.f);
        v1.w = fmaxf(acc[i][7] + bvals[7], 0.f);
        *(float4*)&C[(long)gr * 128 + tx * 8]     = v0;
        *(float4*)&C[(long)gr * 128 + tx * 8 + 4] = v1;
    }
}

// ---------------- launch --------------------------------------------------
extern "C" void kernel_launch(void* const* d_in, const int* in_sizes, int n_in,
                              void* d_out, int out_size) {
    const float* x      = (const float*)d_in[0];
    const int*   mei    = (const int*)d_in[1];
    const int*   tei    = (const int*)d_in[2];
    const float* tw     = (const float*)d_in[3];
    const float* W_rel  = (const float*)d_in[4];
    const float* b_rel  = (const float*)d_in[5];
    const float* W_root = (const float*)d_in[6];
    const float* W_mu   = (const float*)d_in[7];
    const float* b_mu   = (const float*)d_in[8];
    float* out = (float*)d_out;

    int N     = in_sizes[0] / DIM_D;       // 100000
    int E_msg = in_sizes[1] / 2;           // 1,600,000
    int E_tgt = in_sizes[2] / 2;           // 10,000

    float* agg; float* h;
    cudaGetSymbolAddress((void**)&agg, g_agg);
    cudaGetSymbolAddress((void**)&h, g_h);

    // 1) zero agg
    {
        int n4 = N * (DIM_D / 4);
        int threads = 256;
        int blocks = (n4 + threads - 1) / threads;
        zero_kernel<<<blocks, threads>>>((float4*)agg, n4);
    }

    // 2) scatter-aggregate (message edges + flipped target edges)
    {
        int E = E_msg + E_tgt;
        long total = (long)E * 64;
        int threads = 256;
        int blocks = (int)((total + threads - 1) / threads);
        scatter_kernel<<<blocks, threads>>>((const float4*)x, mei, E_msg,
                                            tei, tw, E_tgt, (float4*)agg);
    }

    // 3) h = relu(agg @ W_rel + x @ W_root + b_rel)
    {
        int blocks = (N + BM - 1) / BM;
        gemm_bias_relu<<<blocks, 256>>>(agg, W_rel, x, W_root, b_rel, h,
                                        N, DIM_D);
    }

    // 4) out = relu(h @ W_mu + b_mu)   (eval-mode rrelu is identity on relu output)
    {
        int blocks = (N + BM - 1) / BM;
        gemm_bias_relu<<<blocks, 256>>>(h, W_mu, nullptr, nullptr, b_mu, out,
                                        N, DIM_O);
    }

    // 5) second output: target_edge_weights appended after the [N,128] tensor
    long main_elems = (long)N * DIM_O;
    if ((long)out_size >= main_elems + E_tgt) {
        cudaMemcpyAsync(out + main_elems, tw, (size_t)E_tgt * sizeof(float),
                        cudaMemcpyDeviceToDevice);
    }
}